// round 5
// baseline (speedup 1.0000x reference)
#include <cuda_runtime.h>
#include <cuda_bf16.h>

// Shapes (fixed): B=1, C=8, O=8, G=12, X=Y=Z=12, H=8, W=40, Bb=7 (basis), 27 taps
// x      : (1,8,12,12,12,8,40) f32   strides: c 552960, xi 46080, yi 3840, zi 320, h 40, w 1
// weight : (8,8,3,3,3,7)       f32   o 1512, c 189, f 7, b 1
// bias   : (8,3,3,3)           f32
// basis  : (12,7,3,3)          f32   g 63, b 9, u 3, v 1
// out    : (1,96,12,12,12,8,40) f32  go 552960, same spatial strides as x
//
// Factored algorithm:
//   Y[b,o,h,w]   = sum_{c,f} x[c, n+f, h, w] * weight[o,c,f,b]          (per n)
//   out[g*8+o,.] = biasSum[o] + sum_{b,u,v} basis[(g+border)%12,b,u,v] * Y[b,o,hh0+u,ww0+v]
// Phase 2 is separable per o -> each CTA handles one half (4 o's) of one cell.
// Grid = 729 cells x 2 halves = 1458 CTAs of 320 threads; smem 92KB -> 2 CTAs/SM.

#define NT 320
// smem floats: sW[216*32] + sB2[2*63*16] + sBiasS[16] + sX[2*2560] + sY[28*320]
#define SMEM_FLOATS (6912 + 2016 + 16 + 5120 + 8960)
#define SMEM_BYTES (SMEM_FLOATS * 4)

__device__ float gW[216 * 64];      // [(c*27+f)][o*8+b], b==7 zero-padded
__device__ float gB2[2 * 63 * 16];  // [shift][kk][g], g>=12 zero-padded
__device__ float gBiasS[8];

// zero_shell + one-shot prep (first few blocks also build gW/gB2/gBiasS).
__global__ __launch_bounds__(512)
void zero_prep(const float* __restrict__ weight,
               const float* __restrict__ bias,
               const float* __restrict__ basis,
               float* __restrict__ out)
{
    const int blk = blockIdx.x, tid = threadIdx.x;

    if (blk < 27) {               // 27*512 = 13824 = gW elements
        int idx = blk * 512 + tid;
        int row = idx >> 6;       // c*27+f
        int col = idx & 63;       // o*8+b
        int b = col & 7, o = col >> 3;
        int c = row / 27, f = row % 27;
        gW[idx] = (b < 7) ? weight[o * 1512 + c * 189 + f * 7 + b] : 0.f;
    } else if (blk == 27) {
        if (tid < 8) {
            float s = 0.f;
            #pragma unroll
            for (int t = 0; t < 27; t++) s += bias[tid * 27 + t];
            gBiasS[tid] = s;
        }
        for (int i = tid; i < 2016; i += 512) {
            int s  = i / 1008;
            int kk = (i % 1008) >> 4;
            int g  = i & 15;
            int ge = g + s; if (ge >= 12) ge -= 12;
            gB2[i] = (g < 12) ? basis[ge * 63 + kk] : 0.f;
        }
    }

    // shell zeroing: one thread = one float4 slot; interior skipped
    const int idx   = blk * 512 + tid;
    const int cellE = idx / 80;
    const int s4    = idx % 80;
    const int go    = cellE / 1728;
    const int cell  = cellE % 1728;
    const int cx = cell / 144, cy = (cell / 12) % 12, cz = cell % 12;
    if (cx >= 1 && cx <= 9 && cy >= 1 && cy <= 9 && cz >= 1 && cz <= 9) return;
    reinterpret_cast<float4*>(out + (size_t)go * 552960 + (size_t)cell * 320)[s4] =
        make_float4(0.f, 0.f, 0.f, 0.f);
}

__global__ __launch_bounds__(NT, 2)
void gconv_main(const float* __restrict__ x, float* __restrict__ out)
{
    extern __shared__ float smem[];
    float* sW     = smem;            // [216][32]  (c*27+f) x (o_local*8+b)
    float* sB2    = sW + 6912;       // [2][63][16]
    float* sBiasS = sB2 + 2016;      // [8] (+8 pad)
    float* sX     = sBiasS + 16;     // [2][8][320] double-buffered plane
    float* sY     = sX + 5120;       // [28][320]  (o_local*7+b) x pix

    const int tid  = threadIdx.x;
    const int cell = blockIdx.x >> 1;
    const int half = blockIdx.x & 1;
    const int xi = cell / 81, yi = (cell / 9) % 9, zi = cell % 9;

    // ---- stage constants ----
    {
        float4* sW4 = reinterpret_cast<float4*>(sW);
        const float4* gW4 = reinterpret_cast<const float4*>(gW);
        for (int i = tid; i < 1728; i += NT) {
            int row = i >> 3, c4 = i & 7;
            sW4[i] = gW4[row * 16 + half * 8 + c4];
        }
        float4* sB24 = reinterpret_cast<float4*>(sB2);
        const float4* gB24 = reinterpret_cast<const float4*>(gB2);
        for (int i = tid; i < 504; i += NT) sB24[i] = gB24[i];
        if (tid < 8) sBiasS[tid] = gBiasS[tid];
    }

    // ---- Phase 1: Y[o_local*7+b][pix], o_local = tid%4, pixel group tid/4 ----
    const int t_o = tid & 3;
    const int t_q = tid >> 2;          // 0..79, pixels 4*t_q..4*t_q+3
    const int cA  = tid / 80;          // staging: c row (0..3), +4 for second load
    const int p4  = tid % 80;

    float acc[7][4];
    #pragma unroll
    for (int i = 0; i < 7; i++)
        #pragma unroll
        for (int j = 0; j < 4; j++) acc[i][j] = 0.f;

    const float* xn = x + (size_t)xi * 46080 + (size_t)yi * 3840 + (size_t)zi * 320;

    // prefetch plane 0 into registers
    float4 pre0, pre1;
    {
        const float4* xb4 = reinterpret_cast<const float4*>(xn);
        pre0 = xb4[(size_t)cA * 138240 + p4];
        pre1 = xb4[(size_t)(cA + 4) * 138240 + p4];
    }

    for (int f = 0; f < 27; f++) {
        // store prefetched plane into buffer f&1
        float4* dst = reinterpret_cast<float4*>(sX + (f & 1) * 2560);
        dst[cA * 80 + p4] = pre0;
        dst[(cA + 4) * 80 + p4] = pre1;
        // prefetch next plane (LDG latency hidden behind barrier+compute)
        if (f < 26) {
            const int fn = f + 1;
            const int fi = fn / 9, fj = (fn / 3) % 3, fk = fn % 3;
            const float4* xb4 = reinterpret_cast<const float4*>(
                xn + fi * 46080 + fj * 3840 + fk * 320);
            pre0 = xb4[(size_t)cA * 138240 + p4];
            pre1 = xb4[(size_t)(cA + 4) * 138240 + p4];
        }
        __syncthreads();
        const float* xs = sX + (f & 1) * 2560;
        #pragma unroll
        for (int c = 0; c < 8; c++) {
            float4 xv = *reinterpret_cast<const float4*>(xs + c * 320 + t_q * 4);
            const float* wp = sW + (c * 27 + f) * 32 + t_o * 8;
            float4 w0 = *reinterpret_cast<const float4*>(wp);
            float4 w1 = *reinterpret_cast<const float4*>(wp + 4);
            float wr[7] = {w0.x, w0.y, w0.z, w0.w, w1.x, w1.y, w1.z};
            float xr[4] = {xv.x, xv.y, xv.z, xv.w};
            #pragma unroll
            for (int i = 0; i < 7; i++)
                #pragma unroll
                for (int j = 0; j < 4; j++)
                    acc[i][j] = fmaf(wr[i], xr[j], acc[i][j]);
        }
    }
    __syncthreads();
    #pragma unroll
    for (int i = 0; i < 7; i++) {
        float4 v = make_float4(acc[i][0], acc[i][1], acc[i][2], acc[i][3]);
        *reinterpret_cast<float4*>(sY + (t_o * 7 + i) * 320 + t_q * 4) = v;
    }
    __syncthreads();

    // ---- Phase 2: thread = pixel; computes 12 g x 4 o_local ----
    const int h = tid / 40, w = tid % 40;
    const int hh0 = min(max(h, 1), 6) - 1;
    const int ww0 = min(max(w, 1), 38) - 1;
    const int bshift = ((h == 0) | (h == 7) | (w == 0) | (w == 39)) ? 1 : 0;
    const float* bas = sB2 + bshift * 1008;   // [63][16], pre-rotated by shift

    float accP[12][4];
    {
        float b0 = sBiasS[half * 4 + 0], b1 = sBiasS[half * 4 + 1];
        float b2 = sBiasS[half * 4 + 2], b3 = sBiasS[half * 4 + 3];
        #pragma unroll
        for (int g = 0; g < 12; g++) {
            accP[g][0] = b0; accP[g][1] = b1; accP[g][2] = b2; accP[g][3] = b3;
        }
    }

    #pragma unroll
    for (int b = 0; b < 7; b++) {
        #pragma unroll
        for (int u = 0; u < 3; u++) {
            #pragma unroll
            for (int v = 0; v < 3; v++) {
                const int kk = b * 9 + u * 3 + v;
                const int yoff = (hh0 + u) * 40 + (ww0 + v);
                float yv[4];
                #pragma unroll
                for (int ol = 0; ol < 4; ol++)
                    yv[ol] = sY[(ol * 7 + b) * 320 + yoff];
                const float* br = bas + kk * 16;
                float4 g0 = *reinterpret_cast<const float4*>(br);
                float4 g1 = *reinterpret_cast<const float4*>(br + 4);
                float4 g2 = *reinterpret_cast<const float4*>(br + 8);
                float bg[12] = {g0.x, g0.y, g0.z, g0.w,
                                g1.x, g1.y, g1.z, g1.w,
                                g2.x, g2.y, g2.z, g2.w};
                #pragma unroll
                for (int g = 0; g < 12; g++)
                    #pragma unroll
                    for (int ol = 0; ol < 4; ol++)
                        accP[g][ol] = fmaf(bg[g], yv[ol], accP[g][ol]);
            }
        }
    }

    // ---- store interior: out[g*8 + half*4 + ol, xi+1, yi+1, zi+1, h, w] ----
    float* ob = out + (size_t)(xi + 1) * 46080 + (size_t)(yi + 1) * 3840
                    + (size_t)(zi + 1) * 320 + tid
                    + (size_t)half * 4 * 552960;
    #pragma unroll
    for (int g = 0; g < 12; g++)
        #pragma unroll
        for (int ol = 0; ol < 4; ol++)
            ob[(size_t)(g * 8 + ol) * 552960] = accP[g][ol];
}

extern "C" void kernel_launch(void* const* d_in, const int* in_sizes, int n_in,
                              void* d_out, int out_size)
{
    const float* x      = (const float*)d_in[0];
    const float* weight = (const float*)d_in[1];
    const float* bias   = (const float*)d_in[2];
    const float* basis  = (const float*)d_in[3];
    // d_in[4..7] = I, J, T, bias_basis: deterministic clip/border maps, computed inline.
    float* out = (float*)d_out;

    cudaFuncSetAttribute(gconv_main, cudaFuncAttributeMaxDynamicSharedMemorySize, SMEM_BYTES);

    zero_prep<<<25920, 512>>>(weight, bias, basis, out);
    gconv_main<<<1458, NT, SMEM_BYTES>>>(x, out);
}